// round 6
// baseline (speedup 1.0000x reference)
#include <cuda_runtime.h>
#include <cstdint>

#define DIM        2048
#define NE         64
#define M_TOTAL    32768      // 4 * 8192
#define BM         128
#define BK         32
#define NTHREADS   256
#define NBLOCKS    (M_TOTAL / BM)   // 256
#define AS_STRIDE  136        // padded k-major A tile row stride (words)
#define SC_STRIDE  65         // padded scores row stride (words) -> conflict-free

// Deterministic per-block partial softmax-prob sums (no atomics).
__device__ float g_partial[NBLOCKS][NE];

// out layout (float32): [0,65536) indices, [65536,131072) weights, [131072] aux
#define OUT_W_OFF  (M_TOTAL * 2)
#define OUT_AUX    (M_TOTAL * 4)

__device__ __forceinline__ unsigned long long pack2(float v) {
    unsigned long long r;
    asm("mov.b64 %0, {%1, %1};" : "=l"(r) : "f"(v));
    return r;
}

__device__ __forceinline__ void fma2(unsigned long long& acc,
                                     unsigned long long a,
                                     unsigned long long b) {
    asm("fma.rn.f32x2 %0, %1, %2, %0;" : "+l"(acc) : "l"(a), "l"(b));
}

__global__ __launch_bounds__(NTHREADS)
void router_main(const float* __restrict__ x,
                 const float* __restrict__ W,
                 float* __restrict__ out) {
    // smem union: GEMM tiles (As 32x136 + Bs 32x64 = 25.6KB) then scores (128x65 = 33.3KB)
    __shared__ float sm[BM * SC_STRIDE];   // 8320 floats
    __shared__ float s_rowmax[BM];
    __shared__ float s_rowinv[BM];

    float* As = sm;                       // [BK][AS_STRIDE]  k-major, m contiguous
    float* Bs = sm + BK * AS_STRIDE;      // [BK][NE]         k-major, e contiguous

    const int tid = threadIdx.x;
    const int tx  = tid & 15;             // expert group: 4 experts
    const int ty  = tid >> 4;             // row group: 8 rows = 4 row-pairs

    // Per-thread gmem source addresses (fixed across tiles, advance by BK)
    const float* xblk = x + (size_t)blockIdx.x * BM * DIM;
    const int a_row[1] = {0}; (void)a_row;

    // A: 4 float4 per thread; B: 2 float4 per thread
    int aRow[4], aKq[4];
#pragma unroll
    for (int i = 0; i < 4; i++) {
        int idx = tid + i * NTHREADS;
        aRow[i] = idx >> 3;
        aKq[i]  = idx & 7;
    }
    int bEr[2], bKq[2];
#pragma unroll
    for (int i = 0; i < 2; i++) {
        int idx = tid + i * NTHREADS;
        bEr[i] = idx >> 3;
        bKq[i] = idx & 7;
    }

    // acc[pair i][expert j] : packed f32x2 over rows {ty*8+2i, ty*8+2i+1}
    unsigned long long acc[4][4];
#pragma unroll
    for (int i = 0; i < 4; i++)
#pragma unroll
        for (int j = 0; j < 4; j++) acc[i][j] = 0ULL;

    // ---- prologue: load tile 0 into registers, store to smem ----
    float4 aReg[4], bReg[2];
#pragma unroll
    for (int i = 0; i < 4; i++)
        aReg[i] = *reinterpret_cast<const float4*>(xblk + (size_t)aRow[i] * DIM + aKq[i] * 4);
#pragma unroll
    for (int i = 0; i < 2; i++)
        bReg[i] = *reinterpret_cast<const float4*>(W + (size_t)bEr[i] * DIM + bKq[i] * 4);

#pragma unroll
    for (int i = 0; i < 4; i++) {
        int kb = aKq[i] * 4;
        As[(kb + 0) * AS_STRIDE + aRow[i]] = aReg[i].x;
        As[(kb + 1) * AS_STRIDE + aRow[i]] = aReg[i].y;
        As[(kb + 2) * AS_STRIDE + aRow[i]] = aReg[i].z;
        As[(kb + 3) * AS_STRIDE + aRow[i]] = aReg[i].w;
    }
#pragma unroll
    for (int i = 0; i < 2; i++) {
        int kb = bKq[i] * 4;
        Bs[(kb + 0) * NE + bEr[i]] = bReg[i].x;
        Bs[(kb + 1) * NE + bEr[i]] = bReg[i].y;
        Bs[(kb + 2) * NE + bEr[i]] = bReg[i].z;
        Bs[(kb + 3) * NE + bEr[i]] = bReg[i].w;
    }
    __syncthreads();

    for (int k0 = 0; k0 < DIM; k0 += BK) {
        const bool more = (k0 + BK) < DIM;
        // ---- prefetch next tile into registers (LDGs overlap the compute below) ----
        if (more) {
            int kn = k0 + BK;
#pragma unroll
            for (int i = 0; i < 4; i++)
                aReg[i] = *reinterpret_cast<const float4*>(xblk + (size_t)aRow[i] * DIM + kn + aKq[i] * 4);
#pragma unroll
            for (int i = 0; i < 2; i++)
                bReg[i] = *reinterpret_cast<const float4*>(W + (size_t)bEr[i] * DIM + kn + bKq[i] * 4);
        }

        // ---- compute current tile ----
#pragma unroll
        for (int kk = 0; kk < BK; kk++) {
            const float* arow = As + kk * AS_STRIDE + ty * 8;
            unsigned long long a0 = *reinterpret_cast<const unsigned long long*>(arow + 0);
            unsigned long long a1 = *reinterpret_cast<const unsigned long long*>(arow + 2);
            unsigned long long a2 = *reinterpret_cast<const unsigned long long*>(arow + 4);
            unsigned long long a3 = *reinterpret_cast<const unsigned long long*>(arow + 6);
            float4 bv = *reinterpret_cast<const float4*>(Bs + kk * NE + tx * 4);
            unsigned long long b0 = pack2(bv.x);
            unsigned long long b1 = pack2(bv.y);
            unsigned long long b2 = pack2(bv.z);
            unsigned long long b3 = pack2(bv.w);
            fma2(acc[0][0], a0, b0); fma2(acc[0][1], a0, b1);
            fma2(acc[0][2], a0, b2); fma2(acc[0][3], a0, b3);
            fma2(acc[1][0], a1, b0); fma2(acc[1][1], a1, b1);
            fma2(acc[1][2], a1, b2); fma2(acc[1][3], a1, b3);
            fma2(acc[2][0], a2, b0); fma2(acc[2][1], a2, b1);
            fma2(acc[2][2], a2, b2); fma2(acc[2][3], a2, b3);
            fma2(acc[3][0], a3, b0); fma2(acc[3][1], a3, b1);
            fma2(acc[3][2], a3, b2); fma2(acc[3][3], a3, b3);
        }
        __syncthreads();   // everyone done READING this tile

        // ---- store prefetched tile ----
        if (more) {
#pragma unroll
            for (int i = 0; i < 4; i++) {
                int kb = aKq[i] * 4;
                As[(kb + 0) * AS_STRIDE + aRow[i]] = aReg[i].x;
                As[(kb + 1) * AS_STRIDE + aRow[i]] = aReg[i].y;
                As[(kb + 2) * AS_STRIDE + aRow[i]] = aReg[i].z;
                As[(kb + 3) * AS_STRIDE + aRow[i]] = aReg[i].w;
            }
#pragma unroll
            for (int i = 0; i < 2; i++) {
                int kb = bKq[i] * 4;
                Bs[(kb + 0) * NE + bEr[i]] = bReg[i].x;
                Bs[(kb + 1) * NE + bEr[i]] = bReg[i].y;
                Bs[(kb + 2) * NE + bEr[i]] = bReg[i].z;
                Bs[(kb + 3) * NE + bEr[i]] = bReg[i].w;
            }
            __syncthreads();   // tile visible before next compute
        }
    }

    // ---- scatter scores into smem [128][65] ----
#pragma unroll
    for (int i = 0; i < 4; i++) {
        int row0 = ty * 8 + 2 * i;
#pragma unroll
        for (int j = 0; j < 4; j++) {
            int e = tx * 4 + j;
            unsigned long long p = acc[i][j];
            float lo = __uint_as_float((unsigned)(p & 0xffffffffULL));
            float hi = __uint_as_float((unsigned)(p >> 32));
            sm[row0 * SC_STRIDE + e]       = lo;
            sm[(row0 + 1) * SC_STRIDE + e] = hi;
        }
    }
    __syncthreads();

    // ---- phase 1: per-row top-2, weights, row softmax stats ----
    if (tid < BM) {
        const float* srow = sm + tid * SC_STRIDE;
        float v0 = -3.4e38f, v1 = -3.4e38f;
        int i0 = 0, i1 = 0;
#pragma unroll
        for (int e = 0; e < NE; e++) {
            float s = srow[e];
            if (s > v0) { v1 = v0; i1 = i0; v0 = s; i0 = e; }
            else if (s > v1) { v1 = s; i1 = e; }
        }
        float sum = 0.0f;
#pragma unroll
        for (int e = 0; e < NE; e++) sum += __expf(srow[e] - v0);
        s_rowmax[tid] = v0;
        s_rowinv[tid] = 1.0f / sum;

        float t  = __expf(v1 - v0);
        float w0 = 1.0f / (1.0f + t);
        float w1 = t * w0;

        size_t g = (size_t)blockIdx.x * BM + tid;
        out[2 * g]     = (float)i0;
        out[2 * g + 1] = (float)i1;
        out[OUT_W_OFF + 2 * g]     = w0;
        out[OUT_W_OFF + 2 * g + 1] = w1;
    }
    __syncthreads();

    // ---- phase 2: per-expert partial sum of softmax probs over this block's rows ----
    if (tid < NE) {
        float a = 0.0f;
#pragma unroll 8
        for (int r = 0; r < BM; r++) {
            a += __expf(sm[r * SC_STRIDE + tid] - s_rowmax[r]) * s_rowinv[r];
        }
        g_partial[blockIdx.x][tid] = a;
    }
}

__global__ void router_finalize(float* __restrict__ out) {
    __shared__ float red[NE];
    int e = threadIdx.x;  // 64 threads
    float s = 0.0f;
    for (int b = 0; b < NBLOCKS; b++) s += g_partial[b][e];
    s *= (1.0f / (float)M_TOTAL);
    red[e] = s * s;
    __syncthreads();
    if (e == 0) {
        float t = 0.0f;
#pragma unroll
        for (int i = 0; i < NE; i++) t += red[i];
        out[OUT_AUX] = (float)NE * t;
    }
}

extern "C" void kernel_launch(void* const* d_in, const int* in_sizes, int n_in,
                              void* d_out, int out_size) {
    const float* x = (const float*)d_in[0];   // [4, 8192, 2048] f32
    const float* W = (const float*)d_in[1];   // [64, 2048] f32
    float* out = (float*)d_out;

    router_main<<<NBLOCKS, NTHREADS>>>(x, W, out);
    router_finalize<<<1, NE>>>(out);
}